// round 16
// baseline (speedup 1.0000x reference)
#include <cuda_runtime.h>
#include <cuda_fp16.h>
#include <cstdint>

#define T_TOK 2048
#define H_DIM 2048
#define I_DIM 5632
#define N_EXP 8
#define MAXT  72                 /* 64-row tiles: <= 4096/64 + 8 pad tiles */
#define RMAX  (MAXT * 64)        /* 4608 rows */
#define NCH1  (H_DIM / 64)       /* 32 */
#define NCH2  (I_DIM / 64)       /* 88 */
#define WELEM (N_EXP * I_DIM * H_DIM)
#define N4W   (WELEM / 4)
#define CVTB  8192

// ---------------- scratch (device globals; allocation-free) -----------------
__device__ uint32_t d_wg16[WELEM / 2];
__device__ uint32_t d_wu16[WELEM / 2];
__device__ uint32_t d_wd16[WELEM / 2];
__device__ uint32_t d_x16[RMAX * H_DIM / 2];
__device__ uint32_t d_a16[(size_t)RMAX * I_DIM / 2];
__device__ float d_ys [RMAX * H_DIM];
__device__ int   d_topi[T_TOK * 2];
__device__ float d_topw[T_TOK * 2];
__device__ int   d_fill[N_EXP];
__device__ int   d_off [N_EXP];
__device__ int   d_tile_expert[MAXT];
__device__ int   d_ntiles;
__device__ float d_row_w[RMAX];
__device__ int   d_row_of[T_TOK * 2];

// ---------------- helpers ----------------------------------------------------
__device__ __forceinline__ uint32_t smem_u32(const void* p) {
    uint32_t a;
    asm("{ .reg .u64 t; cvta.to.shared.u64 t, %1; cvt.u32.u64 %0, t; }" : "=r"(a) : "l"(p));
    return a;
}

__device__ __forceinline__ uint32_t pack2h(float a, float b) {
    union { __half2 h; uint32_t u; } c;
    c.h = __floats2half2_rn(a, b);
    return c.u;
}

__device__ __forceinline__ void mma16816(float* c,
    uint32_t a0, uint32_t a1, uint32_t a2, uint32_t a3, uint32_t b0, uint32_t b1) {
    asm("mma.sync.aligned.m16n8k16.row.col.f32.f16.f16.f32 "
        "{%0,%1,%2,%3}, {%4,%5,%6,%7}, {%8,%9}, {%0,%1,%2,%3};"
        : "+f"(c[0]), "+f"(c[1]), "+f"(c[2]), "+f"(c[3])
        : "r"(a0), "r"(a1), "r"(a2), "r"(a3), "r"(b0), "r"(b1));
}

#define LDSM4(r, a) \
    asm volatile("ldmatrix.sync.aligned.m8n8.x4.shared.b16 {%0,%1,%2,%3}, [%4];" \
        : "=r"((r)[0]), "=r"((r)[1]), "=r"((r)[2]), "=r"((r)[3]) : "r"(a))

#define CPA(dst, src) \
    asm volatile("cp.async.cg.shared.global [%0], [%1], 16;" :: "r"(dst), "l"(src))
#define CPC() asm volatile("cp.async.commit_group;" ::: "memory")
#define CPW(n) asm volatile("cp.async.wait_group %0;" :: "n"(n) : "memory")

__device__ __forceinline__ float silu(float g) { return g / (1.f + __expf(-g)); }

// ---------------- k_pre: weight conversion + router ---------------------------
__global__ void k_pre(const float4* __restrict__ wg, const float4* __restrict__ wu,
                      const float4* __restrict__ wd,
                      const float* __restrict__ x, const float* __restrict__ gw) {
    if (blockIdx.x < CVTB) {
        const size_t total = 3u * (size_t)N4W;
        for (size_t i = (size_t)blockIdx.x * blockDim.x + threadIdx.x; i < total;
             i += (size_t)CVTB * blockDim.x) {
            const float4* s;
            uint2* d;
            size_t j;
            if (i < (size_t)N4W)           { s = wg; d = (uint2*)d_wg16; j = i; }
            else if (i < 2u * (size_t)N4W) { s = wu; d = (uint2*)d_wu16; j = i - N4W; }
            else                           { s = wd; d = (uint2*)d_wd16; j = i - 2u * (size_t)N4W; }
            float4 v = s[j];
            d[j] = make_uint2(pack2h(v.x, v.y), pack2h(v.z, v.w));
        }
        return;
    }

    int warp = threadIdx.x >> 5, lane = threadIdx.x & 31;
    int t = (blockIdx.x - CVTB) * 8 + warp;
    const float* xr = x + (size_t)t * H_DIM;
    float acc[N_EXP];
#pragma unroll
    for (int e = 0; e < N_EXP; e++) acc[e] = 0.f;
    for (int h = lane; h < H_DIM; h += 32) {
        float xv = xr[h];
#pragma unroll
        for (int e = 0; e < N_EXP; e++) acc[e] += xv * gw[e * H_DIM + h];
    }
#pragma unroll
    for (int e = 0; e < N_EXP; e++)
#pragma unroll
        for (int o = 16; o > 0; o >>= 1) acc[e] += __shfl_xor_sync(0xffffffffu, acc[e], o);

    if (lane == 0) {
        float mx = acc[0];
#pragma unroll
        for (int e = 1; e < N_EXP; e++) mx = fmaxf(mx, acc[e]);
        float p[N_EXP], s = 0.f;
#pragma unroll
        for (int e = 0; e < N_EXP; e++) { p[e] = __expf(acc[e] - mx); s += p[e]; }
        float inv = 1.f / s;
#pragma unroll
        for (int e = 0; e < N_EXP; e++) p[e] *= inv;
        int i0 = 0;
#pragma unroll
        for (int e = 1; e < N_EXP; e++) if (p[e] > p[i0]) i0 = e;
        int i1 = (i0 == 0) ? 1 : 0;
#pragma unroll
        for (int e = 0; e < N_EXP; e++) if (e != i0 && p[e] > p[i1]) i1 = e;
        float sw = p[i0] + p[i1];
        d_topi[2 * t] = i0;     d_topw[2 * t]     = p[i0] / sw;
        d_topi[2 * t + 1] = i1; d_topw[2 * t + 1] = p[i1] / sw;
    }
}

// ---------------- offsets: histogram + 64-row segments + fill reset ----------
__global__ void k_offsets() {
    __shared__ int cnt[N_EXP];
    int tid = threadIdx.x;
    if (tid < N_EXP) cnt[tid] = 0;
    __syncthreads();
    for (int i = tid; i < T_TOK * 2; i += blockDim.x)
        atomicAdd(&cnt[d_topi[i]], 1);
    __syncthreads();
    if (tid == 0) {
        int acc = 0;
        for (int e = 0; e < N_EXP; e++) {
            d_off[e] = acc;
            int nt = (cnt[e] + 63) >> 6;
            int tb = acc >> 6;
            for (int j = 0; j < nt; j++) d_tile_expert[tb + j] = e;
            acc += nt << 6;
        }
        d_ntiles = acc >> 6;
    }
    if (tid < N_EXP) d_fill[tid] = 0;
}

__global__ void k_gather(const float* __restrict__ x) {
    int idx = blockIdx.x;
    int t = idx >> 1;
    __shared__ int rs;
    if (threadIdx.x == 0) {
        int e = d_topi[idx];
        int pos = atomicAdd(&d_fill[e], 1);
        int row = d_off[e] + pos;
        d_row_w[row] = d_topw[idx];
        d_row_of[idx] = row;
        rs = row;
    }
    __syncthreads();
    int row = rs;
    const float4* src = (const float4*)(x + (size_t)t * H_DIM);
    uint2* xo = (uint2*)d_x16 + (size_t)row * (H_DIM / 4);
    for (int i = threadIdx.x; i < H_DIM / 4; i += blockDim.x) {
        float4 v = src[i];
        xo[i] = make_uint2(pack2h(v.x, v.y), pack2h(v.z, v.w));
    }
}

// ---------------- GEMM kernels ----------------------------------------------
// 64-row CTA tiles, 128 threads (4 warps), BK=64 fp16, 2 stages, 4 CTAs/SM.
// Stage: A 64 rows x 144B + B 128 rows x 144B = 27648 B.
#define ROWB   144
#define REG_A  (64 * ROWB)                 /* 9216 */
#define STG_SZ (REG_A + 128 * ROWB)        /* 27648 */
#define NST    2
#define GSMEM  (NST * STG_SZ)              /* 55296 */

#define G_ISSUE(c, buf) do {                                                   \
    uint32_t db_ = sbase + (buf) * STG_SZ;                                     \
    size_t so_ = (size_t)(c) * 128;                                            \
    _Pragma("unroll")                                                          \
    for (int k_ = 0; k_ < 12; k_++) CPA(db_ + dsto[k_], srcp[k_] + so_);       \
    CPC();                                                                     \
} while (0)

// GEMM1: act(fp16) = silu(X·Wg^T) * (X·Wu^T).
// CTA 64m x 64n; warps 2m x 2n (warp tile 32x32, gate+up).
// B smem rows: 0-63 gate, 64-127 up.
__global__ void __launch_bounds__(128, 4)
k_gemm1() {
    const int mtile = blockIdx.x;
    if (mtile >= d_ntiles) return;
    const int e  = d_tile_expert[mtile];
    const int r0 = mtile * 64;
    const int i0 = blockIdx.y * 64;

    extern __shared__ char sm[];
    const uint32_t sbase = smem_u32(sm);
    const int tid = threadIdx.x, lane = tid & 31, wid = tid >> 5;
    const int wm = (wid & 1) * 32;
    const int wn = (wid >> 1) * 32;

    // cp.async: 1536 data 16B-chunks/stage, 12 per thread (128 threads)
    const char* srcp[12];
    uint32_t dsto[12];
#pragma unroll
    for (int k = 0; k < 12; k++) {
        int q = k * 128 + tid;
        if (q < 512) {                // A: 64 rows x 8 chunks
            int row = q >> 3, jc = q & 7;
            dsto[k] = (uint32_t)row * ROWB + jc * 16;
            srcp[k] = (const char*)d_x16
                + (size_t)(r0 + row) * (H_DIM * 2) + jc * 16;
        } else {                      // B: 128 rows x 8 chunks (gate|up)
            int idx = q - 512;
            int row = idx >> 3, jc = idx & 7;
            dsto[k] = REG_A + (uint32_t)row * ROWB + jc * 16;
            const char* base = (row < 64) ? (const char*)d_wg16 : (const char*)d_wu16;
            int rr = row & 63;
            srcp[k] = base + ((size_t)e * I_DIM + i0 + rr) * (H_DIM * 2) + jc * 16;
        }
    }

    // ldmatrix lane geometry
    const int lj = lane >> 3, li = lane & 7;
    const uint32_t akj = (uint32_t)((lj >> 1) << 4);
    const uint32_t bkj = (uint32_t)((lj & 1) << 4);
    uint32_t faro[2], fbro[2];
#pragma unroll
    for (int m = 0; m < 2; m++) faro[m] = (uint32_t)(wm + m * 16 + li + ((lj & 1) << 3)) * ROWB + akj;
#pragma unroll
    for (int p = 0; p < 2; p++) fbro[p] = (uint32_t)(wn + p * 16 + li + ((lj >> 1) << 3)) * ROWB + bkj;

    float accg[2][4][4], accu[2][4][4];
#pragma unroll
    for (int m = 0; m < 2; m++)
#pragma unroll
        for (int n = 0; n < 4; n++)
#pragma unroll
            for (int q = 0; q < 4; q++) { accg[m][n][q] = 0.f; accu[m][n][q] = 0.f; }

    G_ISSUE(0, 0);

    for (int c = 0; c < NCH1; c++) {
        CPW(0);
        __syncthreads();
        if (c + 1 < NCH1) G_ISSUE(c + 1, (c + 1) & 1);

        const uint32_t sb = sbase + (c & 1) * STG_SZ;
#pragma unroll
        for (int ks = 0; ks < 4; ks++) {
            const uint32_t kb = ks * 32;
            uint32_t ah[2][4];
#pragma unroll
            for (int m = 0; m < 2; m++) LDSM4(ah[m], sb + faro[m] + kb);
            uint32_t bg[2][4], bu[2][4];
#pragma unroll
            for (int p = 0; p < 2; p++) {
                uint32_t bd = sb + REG_A + fbro[p] + kb;
                LDSM4(bg[p], bd);
                LDSM4(bu[p], bd + 64 * ROWB);
            }
#pragma unroll
            for (int m = 0; m < 2; m++)
#pragma unroll
                for (int nt = 0; nt < 4; nt++) {
                    const int p = nt >> 1, q = (nt & 1) * 2;
                    mma16816(accg[m][nt], ah[m][0], ah[m][1], ah[m][2], ah[m][3], bg[p][q], bg[p][q + 1]);
                    mma16816(accu[m][nt], ah[m][0], ah[m][1], ah[m][2], ah[m][3], bu[p][q], bu[p][q + 1]);
                }
        }
    }

    // epilogue: silu(g)*u fp32 -> fp16
#pragma unroll
    for (int m = 0; m < 2; m++)
#pragma unroll
        for (int nt = 0; nt < 4; nt++) {
            int row = r0 + wm + m * 16 + (lane >> 2);
            int col = i0 + wn + nt * 8 + (lane & 3) * 2;
            float a0 = silu(accg[m][nt][0]) * accu[m][nt][0];
            float a1 = silu(accg[m][nt][1]) * accu[m][nt][1];
            float a2 = silu(accg[m][nt][2]) * accu[m][nt][2];
            float a3 = silu(accg[m][nt][3]) * accu[m][nt][3];
            d_a16[((size_t)row * I_DIM + col) >> 1]       = pack2h(a0, a1);
            d_a16[((size_t)(row + 8) * I_DIM + col) >> 1] = pack2h(a2, a3);
        }
}

// GEMM2: ys = row_w * (act·Wd^T).
// CTA 64m x 128n; warps 1m x 4n (warp tile 64x32).
__global__ void __launch_bounds__(128, 4)
k_gemm2() {
    const int mtile = blockIdx.x;
    if (mtile >= d_ntiles) return;
    const int e  = d_tile_expert[mtile];
    const int r0 = mtile * 64;
    const int h0 = blockIdx.y * 128;

    extern __shared__ char sm[];
    const uint32_t sbase = smem_u32(sm);
    const int tid = threadIdx.x, lane = tid & 31, wid = tid >> 5;
    const int wn = wid * 32;

    const char* srcp[12];
    uint32_t dsto[12];
#pragma unroll
    for (int k = 0; k < 12; k++) {
        int q = k * 128 + tid;
        if (q < 512) {                // A (act): 64 rows x 8 chunks
            int row = q >> 3, jc = q & 7;
            dsto[k] = (uint32_t)row * ROWB + jc * 16;
            srcp[k] = (const char*)d_a16
                + (size_t)(r0 + row) * (I_DIM * 2) + jc * 16;
        } else {                      // B (wd): 128 rows x 8 chunks
            int idx = q - 512;
            int row = idx >> 3, jc = idx & 7;
            dsto[k] = REG_A + (uint32_t)row * ROWB + jc * 16;
            srcp[k] = (const char*)d_wd16
                + ((size_t)e * H_DIM + h0 + row) * (I_DIM * 2) + jc * 16;
        }
    }

    const int lj = lane >> 3, li = lane & 7;
    const uint32_t akj = (uint32_t)((lj >> 1) << 4);
    const uint32_t bkj = (uint32_t)((lj & 1) << 4);
    uint32_t faro[4], fbro[2];
#pragma unroll
    for (int m = 0; m < 4; m++) faro[m] = (uint32_t)(m * 16 + li + ((lj & 1) << 3)) * ROWB + akj;
#pragma unroll
    for (int p = 0; p < 2; p++) fbro[p] = (uint32_t)(wn + p * 16 + li + ((lj >> 1) << 3)) * ROWB + bkj;

    float acc[4][4][4];
#pragma unroll
    for (int m = 0; m < 4; m++)
#pragma unroll
        for (int n = 0; n < 4; n++)
#pragma unroll
            for (int q = 0; q < 4; q++) acc[m][q][0] = acc[m][q][0];  // no-op placate
#pragma unroll
    for (int m = 0; m < 4; m++)
#pragma unroll
        for (int n = 0; n < 4; n++)
#pragma unroll
            for (int q = 0; q < 4; q++) acc[m][n][q] = 0.f;

    G_ISSUE(0, 0);

    for (int c = 0; c < NCH2; c++) {
        CPW(0);
        __syncthreads();
        if (c + 1 < NCH2) G_ISSUE(c + 1, (c + 1) & 1);

        const uint32_t sb = sbase + (c & 1) * STG_SZ;
#pragma unroll
        for (int ks = 0; ks < 4; ks++) {
            const uint32_t kb = ks * 32;
            uint32_t bh[2][4];
#pragma unroll
            for (int p = 0; p < 2; p++) LDSM4(bh[p], sb + REG_A + fbro[p] + kb);
#pragma unroll
            for (int m = 0; m < 4; m++) {
                uint32_t ah[4];
                LDSM4(ah, sb + faro[m] + kb);
#pragma unroll
                for (int nt = 0; nt < 4; nt++) {
                    const int p = nt >> 1, q = (nt & 1) * 2;
                    mma16816(acc[m][nt], ah[0], ah[1], ah[2], ah[3], bh[p][q], bh[p][q + 1]);
                }
            }
        }
    }

#pragma unroll
    for (int m = 0; m < 4; m++) {
        int row = r0 + m * 16 + (lane >> 2);
        float w0 = d_row_w[row];
        float w1 = d_row_w[row + 8];
#pragma unroll
        for (int nt = 0; nt < 4; nt++) {
            int col = h0 + wn + nt * 8 + (lane & 3) * 2;
            float2 o0, o1;
            o0.x = acc[m][nt][0] * w0;
            o0.y = acc[m][nt][1] * w0;
            o1.x = acc[m][nt][2] * w1;
            o1.y = acc[m][nt][3] * w1;
            *(float2*)(d_ys + (size_t)row * H_DIM + col) = o0;
            *(float2*)(d_ys + (size_t)(row + 8) * H_DIM + col) = o1;
        }
    }
}

// ---------------- combine ----------------------------------------------------
__global__ void k_combine(float* __restrict__ out) {
    int t = blockIdx.x;
    int ra = d_row_of[2 * t];
    int rb = d_row_of[2 * t + 1];
    const float4* pa = (const float4*)(d_ys + (size_t)ra * H_DIM);
    const float4* pb = (const float4*)(d_ys + (size_t)rb * H_DIM);
    float4* po = (float4*)(out + (size_t)t * H_DIM);
    for (int i = threadIdx.x; i < H_DIM / 4; i += blockDim.x) {
        float4 a = pa[i], b = pb[i];
        float4 o;
        o.x = a.x + b.x; o.y = a.y + b.y; o.z = a.z + b.z; o.w = a.w + b.w;
        po[i] = o;
    }
}

// ---------------- launch -----------------------------------------------------
extern "C" void kernel_launch(void* const* d_in, const int* in_sizes, int n_in,
                              void* d_out, int out_size) {
    const float* x  = (const float*)d_in[0];
    const float* gw = (const float*)d_in[1];
    const float* wg = (const float*)d_in[2];
    const float* wu = (const float*)d_in[3];
    const float* wd = (const float*)d_in[4];
    float* out = (float*)d_out;

    cudaFuncSetAttribute(k_gemm1, cudaFuncAttributeMaxDynamicSharedMemorySize, GSMEM);
    cudaFuncSetAttribute(k_gemm2, cudaFuncAttributeMaxDynamicSharedMemorySize, GSMEM);

    k_pre<<<CVTB + T_TOK / 8, 256>>>((const float4*)wg, (const float4*)wu,
                                     (const float4*)wd, x, gw);
    k_offsets<<<1, 256>>>();
    k_gather<<<T_TOK * 2, 256>>>(x);

    dim3 g1(MAXT, I_DIM / 64);
    k_gemm1<<<g1, 128, GSMEM>>>();

    dim3 g2(MAXT, H_DIM / 128);
    k_gemm2<<<g2, 128, GSMEM>>>();

    k_combine<<<T_TOK, 256>>>(out);
}

// round 17
// speedup vs baseline: 1.0586x; 1.0586x over previous
#include <cuda_runtime.h>
#include <cuda_fp16.h>
#include <cstdint>

#define T_TOK 2048
#define H_DIM 2048
#define I_DIM 5632
#define N_EXP 8
#define MAXT  40
#define RMAX  (MAXT * 128)
#define NCH1  (H_DIM / 64)   /* 32 */
#define NCH2  (I_DIM / 64)   /* 88 */
#define WELEM (N_EXP * I_DIM * H_DIM)
#define N4W   (WELEM / 4)    /* float4s per tensor: 23068672 */
#define CVTB  8192           /* converter blocks in k_pre */

// ---------------- scratch (device globals; allocation-free) -----------------
__device__ uint32_t d_wg16[WELEM / 2];
__device__ uint32_t d_wu16[WELEM / 2];
__device__ uint32_t d_wd16[WELEM / 2];
__device__ uint32_t d_x16[RMAX * H_DIM / 2];
__device__ uint32_t d_a16[(size_t)RMAX * I_DIM / 2];
__device__ float d_ys [RMAX * H_DIM];
__device__ int   d_topi[T_TOK * 2];
__device__ float d_topw[T_TOK * 2];
__device__ int   d_fill[N_EXP];
__device__ int   d_off [N_EXP];
__device__ int   d_tile_expert[MAXT];
__device__ int   d_ntiles;
__device__ float d_row_w[RMAX];
__device__ int   d_row_of[T_TOK * 2];

// ---------------- helpers ----------------------------------------------------
__device__ __forceinline__ uint32_t smem_u32(const void* p) {
    uint32_t a;
    asm("{ .reg .u64 t; cvta.to.shared.u64 t, %1; cvt.u32.u64 %0, t; }" : "=r"(a) : "l"(p));
    return a;
}

__device__ __forceinline__ uint32_t pack2h(float a, float b) {
    union { __half2 h; uint32_t u; } c;
    c.h = __floats2half2_rn(a, b);
    return c.u;
}

__device__ __forceinline__ void mma16816(float* c,
    uint32_t a0, uint32_t a1, uint32_t a2, uint32_t a3, uint32_t b0, uint32_t b1) {
    asm("mma.sync.aligned.m16n8k16.row.col.f32.f16.f16.f32 "
        "{%0,%1,%2,%3}, {%4,%5,%6,%7}, {%8,%9}, {%0,%1,%2,%3};"
        : "+f"(c[0]), "+f"(c[1]), "+f"(c[2]), "+f"(c[3])
        : "r"(a0), "r"(a1), "r"(a2), "r"(a3), "r"(b0), "r"(b1));
}

#define LDSM4(r, a) \
    asm volatile("ldmatrix.sync.aligned.m8n8.x4.shared.b16 {%0,%1,%2,%3}, [%4];" \
        : "=r"((r)[0]), "=r"((r)[1]), "=r"((r)[2]), "=r"((r)[3]) : "r"(a))

#define CPA(dst, src) \
    asm volatile("cp.async.cg.shared.global [%0], [%1], 16;" :: "r"(dst), "l"(src))
#define CPC() asm volatile("cp.async.commit_group;" ::: "memory")
#define CPW(n) asm volatile("cp.async.wait_group %0;" :: "n"(n) : "memory")

__device__ __forceinline__ float silu(float g) { return g / (1.f + __expf(-g)); }

// ---------------- k_pre: weight conversion (blocks 0..CVTB-1) + router ------
__global__ void k_pre(const float4* __restrict__ wg, const float4* __restrict__ wu,
                      const float4* __restrict__ wd,
                      const float* __restrict__ x, const float* __restrict__ gw) {
    if (blockIdx.x < CVTB) {
        const size_t total = 3u * (size_t)N4W;
        for (size_t i = (size_t)blockIdx.x * blockDim.x + threadIdx.x; i < total;
             i += (size_t)CVTB * blockDim.x) {
            const float4* s;
            uint2* d;
            size_t j;
            if (i < (size_t)N4W)           { s = wg; d = (uint2*)d_wg16; j = i; }
            else if (i < 2u * (size_t)N4W) { s = wu; d = (uint2*)d_wu16; j = i - N4W; }
            else                           { s = wd; d = (uint2*)d_wd16; j = i - 2u * (size_t)N4W; }
            float4 v = s[j];
            d[j] = make_uint2(pack2h(v.x, v.y), pack2h(v.z, v.w));
        }
        return;
    }

    // Router: one warp per token; writes d_topi/d_topw only (no counters).
    int warp = threadIdx.x >> 5, lane = threadIdx.x & 31;
    int t = (blockIdx.x - CVTB) * 8 + warp;
    const float* xr = x + (size_t)t * H_DIM;
    float acc[N_EXP];
#pragma unroll
    for (int e = 0; e < N_EXP; e++) acc[e] = 0.f;
    for (int h = lane; h < H_DIM; h += 32) {
        float xv = xr[h];
#pragma unroll
        for (int e = 0; e < N_EXP; e++) acc[e] += xv * gw[e * H_DIM + h];
    }
#pragma unroll
    for (int e = 0; e < N_EXP; e++)
#pragma unroll
        for (int o = 16; o > 0; o >>= 1) acc[e] += __shfl_xor_sync(0xffffffffu, acc[e], o);

    if (lane == 0) {
        float mx = acc[0];
#pragma unroll
        for (int e = 1; e < N_EXP; e++) mx = fmaxf(mx, acc[e]);
        float p[N_EXP], s = 0.f;
#pragma unroll
        for (int e = 0; e < N_EXP; e++) { p[e] = __expf(acc[e] - mx); s += p[e]; }
        float inv = 1.f / s;
#pragma unroll
        for (int e = 0; e < N_EXP; e++) p[e] *= inv;
        int i0 = 0;
#pragma unroll
        for (int e = 1; e < N_EXP; e++) if (p[e] > p[i0]) i0 = e;
        int i1 = (i0 == 0) ? 1 : 0;
#pragma unroll
        for (int e = 0; e < N_EXP; e++) if (e != i0 && p[e] > p[i1]) i1 = e;
        float sw = p[i0] + p[i1];
        d_topi[2 * t] = i0;     d_topw[2 * t]     = p[i0] / sw;
        d_topi[2 * t + 1] = i1; d_topw[2 * t + 1] = p[i1] / sw;
    }
}

// ---------------- offsets: histogram d_topi, build segments, reset fill ------
__global__ void k_offsets() {
    __shared__ int cnt[N_EXP];
    int tid = threadIdx.x;
    if (tid < N_EXP) cnt[tid] = 0;
    __syncthreads();
    for (int i = tid; i < T_TOK * 2; i += blockDim.x)
        atomicAdd(&cnt[d_topi[i]], 1);
    __syncthreads();
    if (tid == 0) {
        int acc = 0;
        for (int e = 0; e < N_EXP; e++) {
            d_off[e] = acc;
            int nt = (cnt[e] + 127) >> 7;
            int tb = acc >> 7;
            for (int j = 0; j < nt; j++) d_tile_expert[tb + j] = e;
            acc += nt << 7;
        }
        d_ntiles = acc >> 7;
    }
    if (tid < N_EXP) d_fill[tid] = 0;
}

__global__ void k_gather(const float* __restrict__ x) {
    int idx = blockIdx.x;
    int t = idx >> 1;
    __shared__ int rs;
    if (threadIdx.x == 0) {
        int e = d_topi[idx];
        int pos = atomicAdd(&d_fill[e], 1);
        int row = d_off[e] + pos;
        d_row_w[row] = d_topw[idx];
        d_row_of[idx] = row;
        rs = row;
    }
    __syncthreads();
    int row = rs;
    const float4* src = (const float4*)(x + (size_t)t * H_DIM);
    uint2* xo = (uint2*)d_x16 + (size_t)row * (H_DIM / 4);
    for (int i = threadIdx.x; i < H_DIM / 4; i += blockDim.x) {
        float4 v = src[i];
        xo[i] = make_uint2(pack2h(v.x, v.y), pack2h(v.z, v.w));
    }
}

// ---------------- GEMM kernels (byte-identical to the 1133us R14 config) ----
// BK = 64 (fp16). Per-stage: A 128 rows x 144B (128B data + 16B pad),
// B 128 rows x 144B. 3 stages, 2 CTAs/SM.
#define ROWB   144
#define REG_A  (128 * ROWB)                /* 18432 */
#define STG_SZ (2 * REG_A)                 /* 36864 */
#define NST    3
#define GSMEM  (NST * STG_SZ)              /* 110592 */

#define G_ISSUE(c, buf) do {                                                   \
    uint32_t db_ = sbase + (buf) * STG_SZ;                                     \
    size_t so_ = (size_t)(c) * 128;                                            \
    _Pragma("unroll")                                                          \
    for (int k_ = 0; k_ < 8; k_++) CPA(db_ + dsto[k_], srcp[k_] + so_);        \
    CPC();                                                                     \
} while (0)

// GEMM1: act(fp16) = silu(X·Wg^T) * (X·Wu^T).  CTA 128m x 64n; warps 4m x 2n.
__global__ void __launch_bounds__(256, 2)
k_gemm1() {
    const int mtile = blockIdx.x;
    if (mtile >= d_ntiles) return;
    const int e  = d_tile_expert[mtile];
    const int r0 = mtile * 128;
    const int i0 = blockIdx.y * 64;

    extern __shared__ char sm[];
    const uint32_t sbase = smem_u32(sm);
    const int tid = threadIdx.x, lane = tid & 31, wid = tid >> 5;
    const int wm = (wid & 3) * 32;
    const int wn = (wid >> 2) * 32;

    const char* srcp[8];
    uint32_t dsto[8];
#pragma unroll
    for (int k = 0; k < 8; k++) {
        int q = k * 256 + tid;
        if (q < 1024) {
            int row = q >> 3, jc = q & 7;
            dsto[k] = (uint32_t)row * ROWB + jc * 16;
            srcp[k] = (const char*)d_x16
                + (size_t)(r0 + row) * (H_DIM * 2) + jc * 16;
        } else {
            int idx = q - 1024;
            int row = idx >> 3, jc = idx & 7;
            dsto[k] = REG_A + (uint32_t)row * ROWB + jc * 16;
            const char* base = (row < 64) ? (const char*)d_wg16 : (const char*)d_wu16;
            int rr = row & 63;
            srcp[k] = base + ((size_t)e * I_DIM + i0 + rr) * (H_DIM * 2) + jc * 16;
        }
    }

    const int lj = lane >> 3, li = lane & 7;
    const uint32_t akj = (uint32_t)((lj >> 1) << 4);
    const uint32_t bkj = (uint32_t)((lj & 1) << 4);
    uint32_t faro[2], fbro[2];
#pragma unroll
    for (int m = 0; m < 2; m++) faro[m] = (uint32_t)(wm + m * 16 + li + ((lj & 1) << 3)) * ROWB + akj;
#pragma unroll
    for (int p = 0; p < 2; p++) fbro[p] = (uint32_t)(wn + p * 16 + li + ((lj >> 1) << 3)) * ROWB + bkj;

    float accg[2][4][4], accu[2][4][4];
#pragma unroll
    for (int m = 0; m < 2; m++)
#pragma unroll
        for (int n = 0; n < 4; n++)
#pragma unroll
            for (int q = 0; q < 4; q++) { accg[m][n][q] = 0.f; accu[m][n][q] = 0.f; }

    G_ISSUE(0, 0); G_ISSUE(1, 1);
    int cbuf = 0, ibuf = 2;

    for (int c = 0; c < NCH1; c++) {
        if (c + 1 < NCH1) { CPW(1); } else { CPW(0); }
        __syncthreads();
        if (c + 2 < NCH1) {
            G_ISSUE(c + 2, ibuf);
            ibuf = (ibuf + 1 == NST) ? 0 : ibuf + 1;
        }

        const uint32_t sb = sbase + cbuf * STG_SZ;
        cbuf = (cbuf + 1 == NST) ? 0 : cbuf + 1;

#pragma unroll
        for (int ks = 0; ks < 4; ks++) {
            const uint32_t kb = ks * 32;
            uint32_t ah[2][4];
#pragma unroll
            for (int m = 0; m < 2; m++) LDSM4(ah[m], sb + faro[m] + kb);
            uint32_t bg[2][4], bu[2][4];
#pragma unroll
            for (int p = 0; p < 2; p++) {
                uint32_t bd = sb + REG_A + fbro[p] + kb;
                LDSM4(bg[p], bd);
                LDSM4(bu[p], bd + 64 * ROWB);
            }
#pragma unroll
            for (int m = 0; m < 2; m++)
#pragma unroll
                for (int nt = 0; nt < 4; nt++) {
                    const int p = nt >> 1, q = (nt & 1) * 2;
                    mma16816(accg[m][nt], ah[m][0], ah[m][1], ah[m][2], ah[m][3], bg[p][q], bg[p][q + 1]);
                    mma16816(accu[m][nt], ah[m][0], ah[m][1], ah[m][2], ah[m][3], bu[p][q], bu[p][q + 1]);
                }
        }
    }

#pragma unroll
    for (int m = 0; m < 2; m++)
#pragma unroll
        for (int nt = 0; nt < 4; nt++) {
            int row = r0 + wm + m * 16 + (lane >> 2);
            int col = i0 + wn + nt * 8 + (lane & 3) * 2;
            float a0 = silu(accg[m][nt][0]) * accu[m][nt][0];
            float a1 = silu(accg[m][nt][1]) * accu[m][nt][1];
            float a2 = silu(accg[m][nt][2]) * accu[m][nt][2];
            float a3 = silu(accg[m][nt][3]) * accu[m][nt][3];
            d_a16[((size_t)row * I_DIM + col) >> 1]       = pack2h(a0, a1);
            d_a16[((size_t)(row + 8) * I_DIM + col) >> 1] = pack2h(a2, a3);
        }
}

// GEMM2: ys = row_w * (act·Wd^T).  CTA 128m x 128n; warps 2m x 4n.
__global__ void __launch_bounds__(256, 2)
k_gemm2() {
    const int mtile = blockIdx.x;
    if (mtile >= d_ntiles) return;
    const int e  = d_tile_expert[mtile];
    const int r0 = mtile * 128;
    const int h0 = blockIdx.y * 128;

    extern __shared__ char sm[];
    const uint32_t sbase = smem_u32(sm);
    const int tid = threadIdx.x, lane = tid & 31, wid = tid >> 5;
    const int wm = (wid & 1) * 64;
    const int wn = (wid >> 1) * 32;

    const char* srcp[8];
    uint32_t dsto[8];
#pragma unroll
    for (int k = 0; k < 8; k++) {
        int q = k * 256 + tid;
        if (q < 1024) {
            int row = q >> 3, jc = q & 7;
            dsto[k] = (uint32_t)row * ROWB + jc * 16;
            srcp[k] = (const char*)d_a16
                + (size_t)(r0 + row) * (I_DIM * 2) + jc * 16;
        } else {
            int idx = q - 1024;
            int row = idx >> 3, jc = idx & 7;
            dsto[k] = REG_A + (uint32_t)row * ROWB + jc * 16;
            srcp[k] = (const char*)d_wd16
                + ((size_t)e * H_DIM + h0 + row) * (I_DIM * 2) + jc * 16;
        }
    }

    const int lj = lane >> 3, li = lane & 7;
    const uint32_t akj = (uint32_t)((lj >> 1) << 4);
    const uint32_t bkj = (uint32_t)((lj & 1) << 4);
    uint32_t faro[4], fbro[2];
#pragma unroll
    for (int m = 0; m < 4; m++) faro[m] = (uint32_t)(wm + m * 16 + li + ((lj & 1) << 3)) * ROWB + akj;
#pragma unroll
    for (int p = 0; p < 2; p++) fbro[p] = (uint32_t)(wn + p * 16 + li + ((lj >> 1) << 3)) * ROWB + bkj;

    float acc[4][4][4];
#pragma unroll
    for (int m = 0; m < 4; m++)
#pragma unroll
        for (int n = 0; n < 4; n++)
#pragma unroll
            for (int q = 0; q < 4; q++) acc[m][n][q] = 0.f;

    G_ISSUE(0, 0); G_ISSUE(1, 1);
    int cbuf = 0, ibuf = 2;

    for (int c = 0; c < NCH2; c++) {
        if (c + 1 < NCH2) { CPW(1); } else { CPW(0); }
        __syncthreads();
        if (c + 2 < NCH2) {
            G_ISSUE(c + 2, ibuf);
            ibuf = (ibuf + 1 == NST) ? 0 : ibuf + 1;
        }

        const uint32_t sb = sbase + cbuf * STG_SZ;
        cbuf = (cbuf + 1 == NST) ? 0 : cbuf + 1;

#pragma unroll
        for (int ks = 0; ks < 4; ks++) {
            const uint32_t kb = ks * 32;
            uint32_t bh[2][4];
#pragma unroll
            for (int p = 0; p < 2; p++) LDSM4(bh[p], sb + REG_A + fbro[p] + kb);
#pragma unroll
            for (int m = 0; m < 4; m++) {
                uint32_t ah[4];
                LDSM4(ah, sb + faro[m] + kb);
#pragma unroll
                for (int nt = 0; nt < 4; nt++) {
                    const int p = nt >> 1, q = (nt & 1) * 2;
                    mma16816(acc[m][nt], ah[0], ah[1], ah[2], ah[3], bh[p][q], bh[p][q + 1]);
                }
            }
        }
    }

#pragma unroll
    for (int m = 0; m < 4; m++) {
        int row = r0 + wm + m * 16 + (lane >> 2);
        float w0 = d_row_w[row];
        float w1 = d_row_w[row + 8];
#pragma unroll
        for (int nt = 0; nt < 4; nt++) {
            int col = h0 + wn + nt * 8 + (lane & 3) * 2;
            float2 o0, o1;
            o0.x = acc[m][nt][0] * w0;
            o0.y = acc[m][nt][1] * w0;
            o1.x = acc[m][nt][2] * w1;
            o1.y = acc[m][nt][3] * w1;
            *(float2*)(d_ys + (size_t)row * H_DIM + col) = o0;
            *(float2*)(d_ys + (size_t)(row + 8) * H_DIM + col) = o1;
        }
    }
}

// ---------------- combine: 2 tokens per block -------------------------------
__global__ void k_combine(float* __restrict__ out) {
    int t = blockIdx.x * 2 + (threadIdx.x >> 7);
    int lt = threadIdx.x & 127;
    int ra = d_row_of[2 * t];
    int rb = d_row_of[2 * t + 1];
    const float4* pa = (const float4*)(d_ys + (size_t)ra * H_DIM);
    const float4* pb = (const float4*)(d_ys + (size_t)rb * H_DIM);
    float4* po = (float4*)(out + (size_t)t * H_DIM);
    for (int i = lt; i < H_DIM / 4; i += 128) {
        float4 a = pa[i], b = pb[i];
        float4 o;
        o.x = a.x + b.x; o.y = a.y + b.y; o.z = a.z + b.z; o.w = a.w + b.w;
        po[i] = o;
    }
}

// ---------------- launch -----------------------------------------------------
extern "C" void kernel_launch(void* const* d_in, const int* in_sizes, int n_in,
                              void* d_out, int out_size) {
    const float* x  = (const float*)d_in[0];
    const float* gw = (const float*)d_in[1];
    const float* wg = (const float*)d_in[2];
    const float* wu = (const float*)d_in[3];
    const float* wd = (const float*)d_in[4];
    float* out = (float*)d_out;

    cudaFuncSetAttribute(k_gemm1, cudaFuncAttributeMaxDynamicSharedMemorySize, GSMEM);
    cudaFuncSetAttribute(k_gemm2, cudaFuncAttributeMaxDynamicSharedMemorySize, GSMEM);

    k_pre<<<CVTB + T_TOK / 8, 256>>>((const float4*)wg, (const float4*)wu,
                                     (const float4*)wd, x, gw);
    k_offsets<<<1, 1024>>>();
    k_gather<<<T_TOK * 2, 256>>>(x);

    dim3 g1(MAXT, I_DIM / 64);
    k_gemm1<<<g1, 256, GSMEM>>>();

    dim3 g2(MAXT, H_DIM / 128);
    k_gemm2<<<g2, 256, GSMEM>>>();

    k_combine<<<T_TOK / 2, 256>>>(out);
}